// round 1
// baseline (speedup 1.0000x reference)
#include <cuda_runtime.h>

#define N_NODES 100000
#define N_EDGES 3200000
#define CH      128
#define NG      256
#define NC      32

// ---------------- scratch (static device globals; no runtime alloc) ----------------
__device__ float g_y[(size_t)N_NODES * CH];    // (x@W)*dinv[src]  (51.2 MB)
__device__ float g_h[(size_t)N_NODES * CH];    // layer output     (51.2 MB)
__device__ float g_dinv[N_NODES];
__device__ int   g_deg[N_NODES];
__device__ int   g_rowptr[N_NODES + 1];
__device__ int   g_cursor[N_NODES];
__device__ int   g_csrc[N_EDGES];              // CSR-by-dst source ids (12.8 MB)
__device__ float g_pool[NG * CH];

// ---------------- CSR construction ----------------
__global__ void init_deg_k() {
    int v = blockIdx.x * blockDim.x + threadIdx.x;
    if (v < N_NODES) g_deg[v] = 1;   // self-loop
}

__global__ void hist_k(const int* __restrict__ dst) {
    int stride = gridDim.x * blockDim.x;
    for (int e = blockIdx.x * blockDim.x + threadIdx.x; e < N_EDGES; e += stride)
        atomicAdd(&g_deg[dst[e]], 1);
}

// single-block exclusive scan of in-degrees -> rowptr/cursor, plus dinv
__global__ void scan_k() {
    __shared__ int ssum[1024];
    const int CHUNK = (N_NODES + 1023) / 1024;   // 98
    int t  = threadIdx.x;
    int lo = t * CHUNK;
    int hi = min(lo + CHUNK, N_NODES);
    int s = 0;
    for (int v = lo; v < hi; v++) s += g_deg[v] - 1;
    ssum[t] = s;
    __syncthreads();
    // inclusive Hillis-Steele
    for (int off = 1; off < 1024; off <<= 1) {
        int val = (t >= off) ? ssum[t - off] : 0;
        __syncthreads();
        ssum[t] += val;
        __syncthreads();
    }
    int run = (t == 0) ? 0 : ssum[t - 1];
    for (int v = lo; v < hi; v++) {
        g_rowptr[v] = run;
        g_cursor[v] = run;
        int d = g_deg[v];
        run += d - 1;
        g_dinv[v] = rsqrtf((float)d);
    }
    if (t == 1023) g_rowptr[N_NODES] = N_EDGES;
}

__global__ void fill_k(const int* __restrict__ src, const int* __restrict__ dst) {
    int stride = gridDim.x * blockDim.x;
    for (int e = blockIdx.x * blockDim.x + threadIdx.x; e < N_EDGES; e += stride) {
        int d = dst[e];
        int p = atomicAdd(&g_cursor[d], 1);
        g_csrc[p] = src[e];
    }
}

// ---------------- GEMM: g_y = (A @ W) * dinv[row] ----------------
// BM=128, BN=128(=CH), 256 threads, 8x8 microtile, W fully smem-resident.
#define GEMM_SMEM ((128 * 128 + 8 * 132) * 4)

__global__ void __launch_bounds__(256) gemm_scale_k(
    const float* __restrict__ Aext, const float* __restrict__ W,
    int use_ext, int M)
{
    extern __shared__ float smem[];
    float* Ws = smem;                       // [128][128]
    float (*As)[132] = (float (*)[132])(smem + 128 * 128);  // [8][132]

    const float* A = use_ext ? Aext : g_h;
    int tid = threadIdx.x;

    // load W (16384 floats) cooperatively
    #pragma unroll
    for (int i = 0; i < 16; i++) {
        int off = tid * 4 + i * 1024;
        *(float4*)&Ws[off] = *(const float4*)&W[off];
    }

    int row0 = blockIdx.x * 128;
    int tx = tid & 15, ty = tid >> 4;

    float acc[8][8];
    #pragma unroll
    for (int i = 0; i < 8; i++)
        #pragma unroll
        for (int j = 0; j < 8; j++) acc[i][j] = 0.f;

    int lr = tid >> 1;            // row within tile this thread loads
    int lc = (tid & 1) * 4;       // 0 or 4
    int grow = row0 + lr;

    for (int kk = 0; kk < CH; kk += 8) {
        float4 av;
        if (grow < M) av = *(const float4*)&A[(size_t)grow * CH + kk + lc];
        else          av = make_float4(0.f, 0.f, 0.f, 0.f);
        __syncthreads();
        As[lc + 0][lr] = av.x;
        As[lc + 1][lr] = av.y;
        As[lc + 2][lr] = av.z;
        As[lc + 3][lr] = av.w;
        __syncthreads();
        #pragma unroll
        for (int k = 0; k < 8; k++) {
            float ar[8], wr[8];
            #pragma unroll
            for (int i = 0; i < 8; i++) ar[i] = As[k][ty * 8 + i];
            *(float4*)&wr[0] = *(float4*)&Ws[(kk + k) * 128 + tx * 8];
            *(float4*)&wr[4] = *(float4*)&Ws[(kk + k) * 128 + tx * 8 + 4];
            #pragma unroll
            for (int i = 0; i < 8; i++)
                #pragma unroll
                for (int j = 0; j < 8; j++)
                    acc[i][j] = fmaf(ar[i], wr[j], acc[i][j]);
        }
    }

    #pragma unroll
    for (int i = 0; i < 8; i++) {
        int r = row0 + ty * 8 + i;
        if (r < M) {
            float dv = g_dinv[r];
            float4 o1, o2;
            o1.x = acc[i][0] * dv; o1.y = acc[i][1] * dv;
            o1.z = acc[i][2] * dv; o1.w = acc[i][3] * dv;
            o2.x = acc[i][4] * dv; o2.y = acc[i][5] * dv;
            o2.z = acc[i][6] * dv; o2.w = acc[i][7] * dv;
            *(float4*)&g_y[(size_t)r * CH + tx * 8]     = o1;
            *(float4*)&g_y[(size_t)r * CH + tx * 8 + 4] = o2;
        }
    }
}

// ---------------- aggregation: g_h[v] = relu(dinv[v]*(sum_{s->v} y[s] + y[v]) + b) ----------------
__global__ void __launch_bounds__(256) aggregate_k(const float* __restrict__ bias) {
    int w = (blockIdx.x * blockDim.x + threadIdx.x) >> 5;
    if (w >= N_NODES) return;
    int lane = threadIdx.x & 31;

    const float4* y4 = (const float4*)g_y;

    float4 a0 = y4[(size_t)w * 32 + lane];   // self-loop term
    float4 a1 = make_float4(0.f, 0.f, 0.f, 0.f);

    int beg = g_rowptr[w], end = g_rowptr[w + 1];
    int i = beg;
    for (; i + 32 <= end; i += 32) {
        int idx = g_csrc[i + lane];
        #pragma unroll
        for (int j = 0; j < 32; j += 2) {
            int s0 = __shfl_sync(0xffffffffu, idx, j);
            int s1 = __shfl_sync(0xffffffffu, idx, j + 1);
            float4 v0 = y4[(size_t)s0 * 32 + lane];
            float4 v1 = y4[(size_t)s1 * 32 + lane];
            a0.x += v0.x; a0.y += v0.y; a0.z += v0.z; a0.w += v0.w;
            a1.x += v1.x; a1.y += v1.y; a1.z += v1.z; a1.w += v1.w;
        }
    }
    if (i < end) {
        int cnt = end - i;
        int idx = g_csrc[min(i + lane, end - 1)];
        for (int j = 0; j < cnt; j++) {
            int s = __shfl_sync(0xffffffffu, idx, j);
            float4 v = y4[(size_t)s * 32 + lane];
            a0.x += v.x; a0.y += v.y; a0.z += v.z; a0.w += v.w;
        }
    }

    float dv = g_dinv[w];
    float4 b = ((const float4*)bias)[lane];
    float4 r;
    r.x = fmaxf(fmaf(a0.x + a1.x, dv, b.x), 0.f);
    r.y = fmaxf(fmaf(a0.y + a1.y, dv, b.y), 0.f);
    r.z = fmaxf(fmaf(a0.z + a1.z, dv, b.z), 0.f);
    r.w = fmaxf(fmaf(a0.w + a1.w, dv, b.w), 0.f);
    ((float4*)g_h)[(size_t)w * 32 + lane] = r;
}

// ---------------- pooling + FC ----------------
__device__ __forceinline__ int lower_bound_i(const int* a, int n, int key) {
    int lo = 0, hi = n;
    while (lo < hi) { int mid = (lo + hi) >> 1; if (a[mid] < key) lo = mid + 1; else hi = mid; }
    return lo;
}

__global__ void pool_k(const int* __restrict__ batch) {
    int g = blockIdx.x;
    __shared__ int slo, shi;
    if (threadIdx.x == 0) {
        slo = lower_bound_i(batch, N_NODES, g);
        shi = lower_bound_i(batch, N_NODES, g + 1);
    }
    __syncthreads();
    int lo = slo, hi = shi;
    int c = threadIdx.x;  // 128 threads
    float s = 0.f;
    for (int r = lo; r < hi; r++) s += g_h[(size_t)r * CH + c];
    float cnt = (float)(hi - lo);
    g_pool[g * CH + c] = s / fmaxf(cnt, 1.0f);
}

__global__ void fc_k(const float* __restrict__ Wfc, const float* __restrict__ bfc,
                     float* __restrict__ out) {
    int g = blockIdx.x;
    int c = threadIdx.x;  // 32 threads
    float acc = bfc[c];
    #pragma unroll 4
    for (int k = 0; k < CH; k++)
        acc = fmaf(g_pool[g * CH + k], Wfc[k * NC + c], acc);
    out[g * NC + c] = acc;
}

// ---------------- launcher ----------------
extern "C" void kernel_launch(void* const* d_in, const int* in_sizes, int n_in,
                              void* d_out, int out_size) {
    const float* x     = (const float*)d_in[0];
    const int*   ei    = (const int*)  d_in[1];
    const int*   batch = (const int*)  d_in[2];
    const float* W1    = (const float*)d_in[3];
    const float* b1    = (const float*)d_in[4];
    const float* W2    = (const float*)d_in[5];
    const float* b2    = (const float*)d_in[6];
    const float* Wfc   = (const float*)d_in[7];
    const float* bfc   = (const float*)d_in[8];
    float* out = (float*)d_out;

    const int* src = ei;
    const int* dst = ei + N_EDGES;

    cudaFuncSetAttribute(gemm_scale_k,
                         cudaFuncAttributeMaxDynamicSharedMemorySize, GEMM_SMEM);

    // CSR build (per call; part of the timed graph)
    init_deg_k<<<(N_NODES + 255) / 256, 256>>>();
    hist_k<<<2048, 256>>>(dst);
    scan_k<<<1, 1024>>>();
    fill_k<<<2048, 256>>>(src, dst);

    int gemm_blocks = (N_NODES + 127) / 128;
    int agg_blocks  = (N_NODES * 32 + 255) / 256;

    // layer 1
    gemm_scale_k<<<gemm_blocks, 256, GEMM_SMEM>>>(x, W1, 1, N_NODES);
    aggregate_k<<<agg_blocks, 256>>>(b1);
    // layer 2
    gemm_scale_k<<<gemm_blocks, 256, GEMM_SMEM>>>(nullptr, W2, 0, N_NODES);
    aggregate_k<<<agg_blocks, 256>>>(b2);
    // pool + fc
    pool_k<<<NG, 128>>>(batch);
    fc_k<<<NG, NC>>>(Wfc, bfc, out);
}